// round 4
// baseline (speedup 1.0000x reference)
#include <cuda_runtime.h>

// ---------------------------------------------------------------------------
// SNN: pool -> fc_in -> 3x LIF recurrent layers -> readout, T=8 steps.
// fp32 throughout (binary spike outputs => must match reference threshold
// decisions; low-precision matmul would flip spikes).
// ---------------------------------------------------------------------------

#define T_STEPS 8
#define BB      32
#define CC      4
#define CHUNK   29
#define HH      64
#define WW      64
#define TPP     14          // (29-3)/2+1
#define HP      32
#define WP      32
#define RR      56          // CC*TPP
#define D_INF   1024
#define H0F     2048
#define H1F     2048
#define H2F     1024
#define NCLS    4
#define MS      (BB*RR)         // 1792 rows per timestep
#define M_ALL   (T_STEPS*MS)    // 14336
#define FOUT    (RR*H2F)        // 57344

// ------------------------- static scratch (no mallocs) ---------------------
__device__ float g_feat  [(size_t)M_ALL * D_INF];   // 58.7 MB
__device__ float g_curin [(size_t)M_ALL * H0F];     // 117.4 MB
__device__ float g_spk_in[(size_t)MS * H0F];
__device__ float g_m_in  [(size_t)MS * H0F];
__device__ float g_spk1  [(size_t)MS * H1F];
__device__ float g_m_h1  [(size_t)MS * H1F];
__device__ float g_spk2  [(size_t)MS * H2F];
__device__ float g_m_h2  [(size_t)MS * H2F];
__device__ float g_m_out [BB * NCLS];

__device__ __forceinline__ float clamp01(float v) {
    return fminf(fmaxf(v, 0.0f), 1.0f);
}

// ------------------------------ zero membranes ------------------------------
__global__ void zero_kernel() {
    int i = blockIdx.x * blockDim.x + threadIdx.x;
    int stride = gridDim.x * blockDim.x;
    for (int k = i; k < MS * H0F; k += stride) { g_m_in[k] = 0.f; g_m_h1[k] = 0.f; }
    for (int k = i; k < MS * H2F; k += stride) g_m_h2[k] = 0.f;
    if (i < BB * NCLS) g_m_out[i] = 0.f;
}

// ------------------------------- avg pool 3d --------------------------------
// out feat[t][b][c*14+tp][hp*32+wp] = mean of x[b,c, t*29+tp*2+kd, hp*2+kh, wp*2+kw]
__global__ void pool_kernel(const float* __restrict__ x) {
    int blk = blockIdx.x;                 // linear over (t,b,c,tp)
    int tp = blk % TPP;
    int c  = (blk / TPP) % CC;
    int b  = (blk / (TPP * CC)) % BB;
    int t  =  blk / (TPP * CC * BB);
    int f0 = t * CHUNK + tp * 2;
    const float* xb = x + ((size_t)(b * CC + c) * 232 + f0) * (HH * WW);
    float* outp = g_feat + ((size_t)((t * BB + b) * RR + (c * TPP + tp))) * D_INF;
    for (int d = threadIdx.x; d < HP * WP; d += blockDim.x) {
        int hp = d >> 5, wp = d & 31;
        const float* p = xb + (hp * 2) * WW + wp * 2;
        float s = 0.f;
#pragma unroll
        for (int kd = 0; kd < 3; kd++) {
            const float* pf = p + kd * (HH * WW);
            float2 a0 = *(const float2*)pf;
            float2 a1 = *(const float2*)(pf + WW);
            s += (a0.x + a0.y) + (a1.x + a1.y);
        }
        outp[d] = s / 12.0f;
    }
}

// --------------------------------- SGEMM ------------------------------------
// C[M,N] = A[M,K] @ B[K,N] + bias.  BM=BN=128, BK=16, 256 threads, 8x8/thread.
// FUSE: instead of writing C, runs the LIF update in the epilogue:
//   reset = (mem > thr); mem' = beta*mem + cur - reset*thr; spk = (mem'-thr)>0
template<bool FUSE>
__global__ void __launch_bounds__(256, 2) sgemm_kernel(
    int M, int N, int K,
    const float* __restrict__ A,
    const float* __restrict__ B,
    const float* __restrict__ bias,
    float* __restrict__ Cout,
    float* __restrict__ mem,
    float* __restrict__ spk,
    const float* __restrict__ betas, int bidx,
    const float* __restrict__ thrs,  int tidx)
{
    const int BKK = 16;
    __shared__ float As[BKK][128 + 4];
    __shared__ float Bs[BKK][128];

    int tid = threadIdx.x;
    int tx = tid & 15;           // 0..15
    int ty = tid >> 4;           // 0..15

    const int bm = blockIdx.y * 128;
    const int bn = blockIdx.x * 128;

    int aRow = tid >> 2;            // 0..63
    int aCol = (tid & 3) * 4;       // 0,4,8,12
    int bRow = tid >> 5;            // 0..7
    int bCol = (tid & 31) * 4;      // 0..124

    const float* Aptr = A + (size_t)(bm + aRow) * K + aCol;
    const float* Bptr = B + (size_t)bRow * N + bn + bCol;

    float acc[8][8];
#pragma unroll
    for (int i = 0; i < 8; i++)
#pragma unroll
        for (int j = 0; j < 8; j++) acc[i][j] = 0.f;

    // ---- initial tile ----
#pragma unroll
    for (int r = 0; r < 2; r++) {
        float4 v = *(const float4*)(Aptr + (size_t)(r * 64) * K);
        As[aCol + 0][aRow + r * 64] = v.x;
        As[aCol + 1][aRow + r * 64] = v.y;
        As[aCol + 2][aRow + r * 64] = v.z;
        As[aCol + 3][aRow + r * 64] = v.w;
    }
#pragma unroll
    for (int r = 0; r < 2; r++) {
        *(float4*)&Bs[bRow + r * 8][bCol] = *(const float4*)(Bptr + (size_t)(r * 8) * N);
    }
    __syncthreads();

    float4 pa[2], pb[2];
    for (int k0 = BKK; k0 <= K; k0 += BKK) {
        bool has_next = (k0 < K);
        if (has_next) {
#pragma unroll
            for (int r = 0; r < 2; r++)
                pa[r] = *(const float4*)(Aptr + (size_t)(r * 64) * K + k0);
#pragma unroll
            for (int r = 0; r < 2; r++)
                pb[r] = *(const float4*)(Bptr + (size_t)(k0 + r * 8) * N);
        }
#pragma unroll
        for (int k = 0; k < BKK; k++) {
            float ra[8], rb[8];
            *(float4*)&ra[0] = *(const float4*)&As[k][ty * 8];
            *(float4*)&ra[4] = *(const float4*)&As[k][ty * 8 + 4];
            *(float4*)&rb[0] = *(const float4*)&Bs[k][tx * 8];
            *(float4*)&rb[4] = *(const float4*)&Bs[k][tx * 8 + 4];
#pragma unroll
            for (int i = 0; i < 8; i++)
#pragma unroll
                for (int j = 0; j < 8; j++)
                    acc[i][j] += ra[i] * rb[j];
        }
        if (has_next) {
            __syncthreads();
#pragma unroll
            for (int r = 0; r < 2; r++) {
                As[aCol + 0][aRow + r * 64] = pa[r].x;
                As[aCol + 1][aRow + r * 64] = pa[r].y;
                As[aCol + 2][aRow + r * 64] = pa[r].z;
                As[aCol + 3][aRow + r * 64] = pa[r].w;
            }
#pragma unroll
            for (int r = 0; r < 2; r++)
                *(float4*)&Bs[bRow + r * 8][bCol] = pb[r];
            __syncthreads();
        }
    }

    // ---- epilogue ----
    float bias_r[8];
#pragma unroll
    for (int j = 0; j < 8; j++) bias_r[j] = bias[bn + tx * 8 + j];

    if (!FUSE) {
#pragma unroll
        for (int i = 0; i < 8; i++) {
            size_t base = (size_t)(bm + ty * 8 + i) * N + bn + tx * 8;
#pragma unroll
            for (int h = 0; h < 2; h++) {
                float4 c4;
                c4.x = acc[i][4 * h + 0] + bias_r[4 * h + 0];
                c4.y = acc[i][4 * h + 1] + bias_r[4 * h + 1];
                c4.z = acc[i][4 * h + 2] + bias_r[4 * h + 2];
                c4.w = acc[i][4 * h + 3] + bias_r[4 * h + 3];
                *(float4*)&Cout[base + 4 * h] = c4;
            }
        }
    } else {
        float beta = clamp01(betas[bidx]);
        float thr  = thrs[tidx];
#pragma unroll
        for (int i = 0; i < 8; i++) {
            size_t base = (size_t)(bm + ty * 8 + i) * N + bn + tx * 8;
#pragma unroll
            for (int h = 0; h < 2; h++) {
                float4 m4 = *(const float4*)&mem[base + 4 * h];
                float4 mn, sp;
                {
                    float cur = acc[i][4 * h + 0] + bias_r[4 * h + 0];
                    mn.x = beta * m4.x + cur - (m4.x > thr ? thr : 0.f);
                    sp.x = (mn.x - thr) > 0.f ? 1.f : 0.f;
                }
                {
                    float cur = acc[i][4 * h + 1] + bias_r[4 * h + 1];
                    mn.y = beta * m4.y + cur - (m4.y > thr ? thr : 0.f);
                    sp.y = (mn.y - thr) > 0.f ? 1.f : 0.f;
                }
                {
                    float cur = acc[i][4 * h + 2] + bias_r[4 * h + 2];
                    mn.z = beta * m4.z + cur - (m4.z > thr ? thr : 0.f);
                    sp.z = (mn.z - thr) > 0.f ? 1.f : 0.f;
                }
                {
                    float cur = acc[i][4 * h + 3] + bias_r[4 * h + 3];
                    mn.w = beta * m4.w + cur - (m4.w > thr ? thr : 0.f);
                    sp.w = (mn.w - thr) > 0.f ? 1.f : 0.f;
                }
                *(float4*)&mem[base + 4 * h] = mn;
                *(float4*)&spk[base + 4 * h] = sp;
            }
        }
    }
}

// ------------------------- LIF on precomputed cur_in ------------------------
__global__ void lif_in_kernel(const float* __restrict__ betas,
                              const float* __restrict__ thrs, int t) {
    int i = blockIdx.x * blockDim.x + threadIdx.x;   // over float4 elements
    float beta = clamp01(betas[0]);
    float thr  = thrs[0];
    const float4* cur4 = (const float4*)(g_curin + (size_t)t * MS * H0F);
    float4* m4p = (float4*)g_m_in;
    float4* s4p = (float4*)g_spk_in;
    float4 m = m4p[i];
    float4 c = cur4[i];
    float4 mn, sp;
    mn.x = beta * m.x + c.x - (m.x > thr ? thr : 0.f); sp.x = (mn.x - thr) > 0.f ? 1.f : 0.f;
    mn.y = beta * m.y + c.y - (m.y > thr ? thr : 0.f); sp.y = (mn.y - thr) > 0.f ? 1.f : 0.f;
    mn.z = beta * m.z + c.z - (m.z > thr ? thr : 0.f); sp.z = (mn.z - thr) > 0.f ? 1.f : 0.f;
    mn.w = beta * m.w + c.w - (m.w > thr ? thr : 0.f); sp.w = (mn.w - thr) > 0.f ? 1.f : 0.f;
    m4p[i] = mn;
    s4p[i] = sp;
}

// --------------------------- readout + output LIF ---------------------------
__global__ void out_kernel(const float* __restrict__ Wout,
                           const float* __restrict__ bout,
                           const float* __restrict__ betas,
                           float* __restrict__ out, int t) {
    __shared__ float red[4][256];
    int b = blockIdx.x;
    int tid = threadIdx.x;
    const float* s = g_spk2 + (size_t)b * FOUT;
    const float4* W4 = (const float4*)Wout;   // W_out row k = 4 floats
    float a0 = 0.f, a1 = 0.f, a2 = 0.f, a3 = 0.f;
    for (int k = tid; k < FOUT; k += 256) {
        float sv = s[k];
        float4 w = W4[k];
        a0 += sv * w.x; a1 += sv * w.y; a2 += sv * w.z; a3 += sv * w.w;
    }
    red[0][tid] = a0; red[1][tid] = a1; red[2][tid] = a2; red[3][tid] = a3;
    __syncthreads();
    for (int off = 128; off > 0; off >>= 1) {
        if (tid < off) {
#pragma unroll
            for (int q = 0; q < 4; q++) red[q][tid] += red[q][tid + off];
        }
        __syncthreads();
    }
    if (tid == 0) {
        float beta = clamp01(betas[3]);
#pragma unroll
        for (int n = 0; n < 4; n++) {
            float cur = red[n][0] + bout[n];
            float m = g_m_out[b * 4 + n];
            float mn = beta * m + cur - (m > 1.0f ? 1.0f : 0.f);
            g_m_out[b * 4 + n] = mn;
            out[t * BB * NCLS + b * NCLS + n] = (mn - 1.0f) > 0.f ? 1.f : 0.f;
        }
    }
}

// ------------------------------- launch --------------------------------------
extern "C" void kernel_launch(void* const* d_in, const int* in_sizes, int n_in,
                              void* d_out, int out_size) {
    const float* x     = (const float*)d_in[0];
    const float* W_in  = (const float*)d_in[1];
    const float* b_in  = (const float*)d_in[2];
    const float* W_h1  = (const float*)d_in[3];
    const float* b_h1  = (const float*)d_in[4];
    const float* W_h2  = (const float*)d_in[5];
    const float* b_h2  = (const float*)d_in[6];
    const float* W_out = (const float*)d_in[7];
    const float* b_out = (const float*)d_in[8];
    const float* betas = (const float*)d_in[9];
    const float* thrs  = (const float*)d_in[10];
    float* out = (float*)d_out;

    float *p_feat, *p_curin, *p_spk_in, *p_m_in, *p_spk1, *p_m_h1, *p_spk2, *p_m_h2;
    cudaGetSymbolAddress((void**)&p_feat,   g_feat);
    cudaGetSymbolAddress((void**)&p_curin,  g_curin);
    cudaGetSymbolAddress((void**)&p_spk_in, g_spk_in);
    cudaGetSymbolAddress((void**)&p_m_in,   g_m_in);
    cudaGetSymbolAddress((void**)&p_spk1,   g_spk1);
    cudaGetSymbolAddress((void**)&p_m_h1,   g_m_h1);
    cudaGetSymbolAddress((void**)&p_spk2,   g_spk2);
    cudaGetSymbolAddress((void**)&p_m_h2,   g_m_h2);

    zero_kernel<<<512, 256>>>();

    // pooling: one block per (t,b,c,tp)
    pool_kernel<<<T_STEPS * BB * CC * TPP, 256>>>(x);

    // GEMM1: cur_in_all = feat @ W_in + b_in   [14336, 2048]
    {
        dim3 grid(H0F / 128, M_ALL / 128);   // (16, 112)
        sgemm_kernel<false><<<grid, 256>>>(M_ALL, H0F, D_INF,
                                           p_feat, W_in, b_in,
                                           p_curin, nullptr, nullptr,
                                           nullptr, 0, nullptr, 0);
    }

    const int n4_lif_in = (MS * H0F) / 4;   // 917504 = 3584 * 256

    for (int t = 0; t < T_STEPS; t++) {
        lif_in_kernel<<<n4_lif_in / 256, 256>>>(betas, thrs, t);

        dim3 g2(H1F / 128, MS / 128);        // (16, 14)
        sgemm_kernel<true><<<g2, 256>>>(MS, H1F, H0F,
                                        p_spk_in, W_h1, b_h1,
                                        nullptr, p_m_h1, p_spk1,
                                        betas, 1, thrs, 1);

        dim3 g3(H2F / 128, MS / 128);        // (8, 14)
        sgemm_kernel<true><<<g3, 256>>>(MS, H2F, H1F,
                                        p_spk1, W_h2, b_h2,
                                        nullptr, p_m_h2, p_spk2,
                                        betas, 2, thrs, 2);

        out_kernel<<<BB, 256>>>(W_out, b_out, betas, out, t);
    }
}

// round 9
// speedup vs baseline: 2.3940x; 2.3940x over previous
#include <cuda_runtime.h>
#include <cuda_fp16.h>
#include <stdint.h>

// ---------------------------------------------------------------------------
// SNN: pool -> fc_in -> 3x LIF layers -> readout, T=8.
// Split-precision fp16 HMMA (mma.sync.m16n8k16) GEMMs, exact for spikes,
// <=2^-22 relative residual for weights (hi+lo split, scale 32).
// No tcgen05 (build targets compute_103 base ISA).
// ---------------------------------------------------------------------------

#define T_STEPS 8
#define BB      32
#define CC      4
#define CHUNK   29
#define HH      64
#define WW      64
#define TPP     14
#define HP      32
#define WP      32
#define RR      56
#define D_INF   1024
#define H0F     2048
#define H1F     2048
#define H2F     1024
#define NCLS    4
#define MS      (BB*RR)         // 1792
#define M_ALL   (T_STEPS*MS)    // 14336
#define FOUT    (RR*H2F)        // 57344

#define SCALE_W 32.0f
#define INV_SW  (1.0f/32.0f)

// GEMM tiling
#define BMT   128
#define BNT   64
#define BKT   32
#define NSTG  3
#define PITCH 80                 // bytes per 64B smem row (padded, ldmatrix-friendly)
#define A_TILE_B (BMT * PITCH)   // 10240
#define B_TILE_B (BNT * PITCH)   // 5120

// ------------------------- static scratch ----------------------------------
__device__ __half g_feat_h[(size_t)M_ALL * D_INF];
__device__ __half g_feat_l[(size_t)M_ALL * D_INF];
__device__ float  g_curin [(size_t)M_ALL * H0F];
__device__ __half g_spkin_h[(size_t)MS * H0F];
__device__ float  g_m_in  [(size_t)MS * H0F];
__device__ __half g_spk1_h[(size_t)MS * H1F];
__device__ float  g_m_h1  [(size_t)MS * H1F];
__device__ float  g_spk2  [(size_t)MS * H2F];
__device__ float  g_m_h2  [(size_t)MS * H2F];
__device__ float  g_m_out [BB * NCLS];
// split/transposed weights [N, K] fp16 (hi/lo), scaled by 32
__device__ __half g_Win_h[(size_t)H0F * D_INF];
__device__ __half g_Win_l[(size_t)H0F * D_INF];
__device__ __half g_Wh1_h[(size_t)H1F * H0F];
__device__ __half g_Wh1_l[(size_t)H1F * H0F];
__device__ __half g_Wh2_h[(size_t)H2F * H1F];
__device__ __half g_Wh2_l[(size_t)H2F * H1F];

__device__ __forceinline__ float clamp01(float v) {
    return fminf(fmaxf(v, 0.0f), 1.0f);
}

__device__ __forceinline__ uint32_t smem_u32(const void* p) {
    uint32_t a;
    asm("{ .reg .u64 t; cvta.to.shared.u64 t, %1; cvt.u32.u64 %0, t; }" : "=r"(a) : "l"(p));
    return a;
}

__device__ __forceinline__ void cp_async16(uint32_t dst, const void* src) {
    asm volatile("cp.async.cg.shared.global [%0], [%1], 16;" :: "r"(dst), "l"(src));
}
__device__ __forceinline__ void ldmx4(uint32_t* r, uint32_t addr) {
    asm volatile("ldmatrix.sync.aligned.m8n8.x4.shared.b16 {%0,%1,%2,%3}, [%4];"
        : "=r"(r[0]), "=r"(r[1]), "=r"(r[2]), "=r"(r[3]) : "r"(addr));
}
__device__ __forceinline__ void mma16816(float* c, const uint32_t* a,
                                         uint32_t b0, uint32_t b1) {
    asm volatile(
        "mma.sync.aligned.m16n8k16.row.col.f32.f16.f16.f32 "
        "{%0,%1,%2,%3}, {%4,%5,%6,%7}, {%8,%9}, {%0,%1,%2,%3};"
        : "+f"(c[0]), "+f"(c[1]), "+f"(c[2]), "+f"(c[3])
        : "r"(a[0]), "r"(a[1]), "r"(a[2]), "r"(a[3]), "r"(b0), "r"(b1));
}

// ------------------------------ zero membranes ------------------------------
__global__ void zero_kernel() {
    int i = blockIdx.x * blockDim.x + threadIdx.x;
    int stride = gridDim.x * blockDim.x;
    for (int k = i; k < MS * H0F; k += stride) { g_m_in[k] = 0.f; g_m_h1[k] = 0.f; }
    for (int k = i; k < MS * H2F; k += stride) g_m_h2[k] = 0.f;
    if (i < BB * NCLS) g_m_out[i] = 0.f;
}

// ------------------------- weight split + transpose -------------------------
// W [K, N] fp32 row-major -> Th, Tl [N, K] fp16, scaled by SCALE_W
__global__ void split_tr_kernel(const float* __restrict__ W,
                                __half* __restrict__ Th, __half* __restrict__ Tl,
                                int K, int N) {
    __shared__ float tile[32][33];
    int n0 = blockIdx.x * 32, k0 = blockIdx.y * 32;
    int tx = threadIdx.x, ty = threadIdx.y;   // 32 x 8
#pragma unroll
    for (int j = 0; j < 32; j += 8)
        tile[ty + j][tx] = W[(size_t)(k0 + ty + j) * N + n0 + tx];
    __syncthreads();
#pragma unroll
    for (int j = 0; j < 32; j += 8) {
        float w = tile[tx][ty + j] * SCALE_W;
        __half hi = __float2half_rn(w);
        __half lo = __float2half_rn(w - __half2float(hi));
        size_t o = (size_t)(n0 + ty + j) * K + k0 + tx;
        Th[o] = hi; Tl[o] = lo;
    }
}

// ------------------------------- avg pool 3d --------------------------------
__global__ void pool_kernel(const float* __restrict__ x) {
    int blk = blockIdx.x;
    int tp = blk % TPP;
    int c  = (blk / TPP) % CC;
    int b  = (blk / (TPP * CC)) % BB;
    int t  =  blk / (TPP * CC * BB);
    int f0 = t * CHUNK + tp * 2;
    const float* xb = x + ((size_t)(b * CC + c) * 232 + f0) * (HH * WW);
    size_t obase = ((size_t)((t * BB + b) * RR + (c * TPP + tp))) * D_INF;
    __half* oh = g_feat_h + obase;
    __half* ol = g_feat_l + obase;
    for (int d = threadIdx.x; d < HP * WP; d += blockDim.x) {
        int hp = d >> 5, wp = d & 31;
        const float* p = xb + (hp * 2) * WW + wp * 2;
        float s = 0.f;
#pragma unroll
        for (int kd = 0; kd < 3; kd++) {
            const float* pf = p + kd * (HH * WW);
            float2 a0 = *(const float2*)pf;
            float2 a1 = *(const float2*)(pf + WW);
            s += (a0.x + a0.y) + (a1.x + a1.y);
        }
        float v = s / 12.0f;
        __half hi = __float2half_rn(v);
        __half lo = __float2half_rn(v - __half2float(hi));
        oh[d] = hi; ol[d] = lo;
    }
}

// ------------------------------ HMMA GEMM -----------------------------------
// C[M,N] = A[M,K] @ B[K,N]; A fp16 (hi + optional lo), B given as [N,K]
// hi/lo fp16 scaled by 32. fp32 accumulate. Epilogue scales by 1/32 + bias.
// EPI: 0 = store float cur; 1 = LIF -> half spk; 2 = LIF -> float spk
template<bool SPLIT_A, int EPI>
__global__ void __launch_bounds__(256, SPLIT_A ? 1 : 2) hgemm_kernel(
    int M, int N, int K,
    const __half* __restrict__ Ah, const __half* __restrict__ Al,
    const __half* __restrict__ Bh, const __half* __restrict__ Bl,
    const float* __restrict__ bias,
    float* __restrict__ Cout,
    float* __restrict__ mem, void* __restrict__ spk,
    const float* __restrict__ betas, int bidx,
    const float* __restrict__ thrs,  int tidx)
{
    extern __shared__ char smem[];
    const int AL_OFF = A_TILE_B;                               // only if SPLIT_A
    const int BH_OFF = SPLIT_A ? 2 * A_TILE_B : A_TILE_B;
    const int BL_OFF = BH_OFF + B_TILE_B;
    const int STAGE  = BL_OFF + B_TILE_B;                      // 30720 / 20480
    uint32_t sb = smem_u32(smem);

    int tid  = threadIdx.x;
    int wid  = tid >> 5, lane = tid & 31;
    const int bm = blockIdx.y * BMT;
    const int bn = blockIdx.x * BNT;
    const int NIT = K / BKT;

    // ---- async loader for one K-chunk into stage s ----
    auto load_chunk = [&](int chunk, int s) {
        uint32_t st = sb + (uint32_t)s * STAGE;
        int k0 = chunk * BKT;
        const int NQ = SPLIT_A ? 6 : 4;
#pragma unroll
        for (int q = 0; q < NQ; q++) {
            int g = tid + (q << 8);
            int r = g >> 2, gran = g & 3;
            if (r < BMT) {
                cp_async16(st + r * PITCH + gran * 16,
                           Ah + (size_t)(bm + r) * K + k0 + gran * 8);
            } else if (SPLIT_A && r < 2 * BMT) {
                int ra = r - BMT;
                cp_async16(st + AL_OFF + ra * PITCH + gran * 16,
                           Al + (size_t)(bm + ra) * K + k0 + gran * 8);
            } else {
                int rb = r - (SPLIT_A ? 2 * BMT : BMT);
                if (rb < BNT) {
                    cp_async16(st + BH_OFF + rb * PITCH + gran * 16,
                               Bh + (size_t)(bn + rb) * K + k0 + gran * 8);
                } else {
                    rb -= BNT;
                    cp_async16(st + BL_OFF + rb * PITCH + gran * 16,
                               Bl + (size_t)(bn + rb) * K + k0 + gran * 8);
                }
            }
        }
    };

    float acc[2][4][4];
#pragma unroll
    for (int i = 0; i < 2; i++)
#pragma unroll
        for (int j = 0; j < 4; j++)
#pragma unroll
            for (int q = 0; q < 4; q++) acc[i][j][q] = 0.f;

    // warp tile: 4x2 warps, each 32(m) x 32(n)
    int mw = wid & 3, nw = wid >> 2;
    uint32_t a_lane = (uint32_t)((mw * 32 + (lane & 15)) * PITCH + ((lane >> 4) << 4));
    uint32_t b_lane = (uint32_t)((nw * 32 + (lane & 7)) * PITCH + ((lane >> 3) << 4));

    // ---- prologue: prefetch NSTG-1 chunks ----
#pragma unroll
    for (int p = 0; p < NSTG - 1; p++) {
        load_chunk(p, p);
        asm volatile("cp.async.commit_group;");
    }

    for (int it = 0; it < NIT; it++) {
        int pf = it + NSTG - 1;
        if (pf < NIT) load_chunk(pf, pf % NSTG);
        asm volatile("cp.async.commit_group;");
        asm volatile("cp.async.wait_group %0;" :: "n"(NSTG - 1));
        __syncthreads();

        uint32_t st = sb + (uint32_t)(it % NSTG) * STAGE;

        uint32_t a[2][2][4];
#pragma unroll
        for (int i = 0; i < 2; i++)
#pragma unroll
            for (int s = 0; s < 2; s++)
                ldmx4(a[i][s], st + a_lane + (uint32_t)(i * 16 * PITCH + s * 32));

        uint32_t bh[4][4], bl[4][4];
#pragma unroll
        for (int j = 0; j < 4; j++)
            ldmx4(bh[j], st + BH_OFF + b_lane + (uint32_t)(j * 8 * PITCH));
#pragma unroll
        for (int j = 0; j < 4; j++)
            ldmx4(bl[j], st + BL_OFF + b_lane + (uint32_t)(j * 8 * PITCH));

#pragma unroll
        for (int i = 0; i < 2; i++)
#pragma unroll
            for (int j = 0; j < 4; j++) {
                mma16816(acc[i][j], a[i][0], bh[j][0], bh[j][1]);
                mma16816(acc[i][j], a[i][1], bh[j][2], bh[j][3]);
                mma16816(acc[i][j], a[i][0], bl[j][0], bl[j][1]);
                mma16816(acc[i][j], a[i][1], bl[j][2], bl[j][3]);
            }

        if (SPLIT_A) {
            uint32_t al[2][2][4];
#pragma unroll
            for (int i = 0; i < 2; i++)
#pragma unroll
                for (int s = 0; s < 2; s++)
                    ldmx4(al[i][s], st + AL_OFF + a_lane + (uint32_t)(i * 16 * PITCH + s * 32));
#pragma unroll
            for (int i = 0; i < 2; i++)
#pragma unroll
                for (int j = 0; j < 4; j++) {
                    mma16816(acc[i][j], al[i][0], bh[j][0], bh[j][1]);
                    mma16816(acc[i][j], al[i][1], bh[j][2], bh[j][3]);
                }
        }
        __syncthreads();
    }

    // ------------------------------ epilogue --------------------------------
    int rg = lane >> 2;
    int cq = (lane & 3) * 2;
    float beta = 0.f, thr = 0.f;
    if (EPI != 0) { beta = clamp01(betas[bidx]); thr = thrs[tidx]; }

#pragma unroll
    for (int i = 0; i < 2; i++) {
#pragma unroll
        for (int j = 0; j < 4; j++) {
            int cn = bn + nw * 32 + j * 8 + cq;
            float bs0 = bias[cn], bs1 = bias[cn + 1];
#pragma unroll
            for (int h = 0; h < 2; h++) {         // row halves (+0, +8)
                int rm = bm + mw * 32 + i * 16 + rg + h * 8;
                float cur0 = acc[i][j][2 * h + 0] * INV_SW + bs0;
                float cur1 = acc[i][j][2 * h + 1] * INV_SW + bs1;
                size_t off = (size_t)rm * N + cn;
                if (EPI == 0) {
                    *(float2*)(Cout + off) = make_float2(cur0, cur1);
                } else {
                    float2 m2 = *(const float2*)(mem + off);
                    float mn0 = beta * m2.x + cur0 - (m2.x > thr ? thr : 0.f);
                    float mn1 = beta * m2.y + cur1 - (m2.y > thr ? thr : 0.f);
                    float sp0 = (mn0 - thr) > 0.f ? 1.f : 0.f;
                    float sp1 = (mn1 - thr) > 0.f ? 1.f : 0.f;
                    *(float2*)(mem + off) = make_float2(mn0, mn1);
                    if (EPI == 1) {
                        *(__half2*)((__half*)spk + off) = __floats2half2_rn(sp0, sp1);
                    } else {
                        *(float2*)((float*)spk + off) = make_float2(sp0, sp1);
                    }
                }
            }
        }
    }
}

// ------------------------- LIF on precomputed cur_in ------------------------
__global__ void lif_in_kernel(const float* __restrict__ betas,
                              const float* __restrict__ thrs, int t) {
    int i = blockIdx.x * blockDim.x + threadIdx.x;   // float4 index
    float beta = clamp01(betas[0]);
    float thr  = thrs[0];
    const float4* cur4 = (const float4*)(g_curin + (size_t)t * MS * H0F);
    float4* m4p = (float4*)g_m_in;
    float4 m = m4p[i];
    float4 c = cur4[i];
    float mn0 = beta * m.x + c.x - (m.x > thr ? thr : 0.f);
    float mn1 = beta * m.y + c.y - (m.y > thr ? thr : 0.f);
    float mn2 = beta * m.z + c.z - (m.z > thr ? thr : 0.f);
    float mn3 = beta * m.w + c.w - (m.w > thr ? thr : 0.f);
    float sp0 = (mn0 - thr) > 0.f ? 1.f : 0.f;
    float sp1 = (mn1 - thr) > 0.f ? 1.f : 0.f;
    float sp2 = (mn2 - thr) > 0.f ? 1.f : 0.f;
    float sp3 = (mn3 - thr) > 0.f ? 1.f : 0.f;
    m4p[i] = make_float4(mn0, mn1, mn2, mn3);
    __half2* hp = (__half2*)g_spkin_h + 2 * (size_t)i;
    hp[0] = __floats2half2_rn(sp0, sp1);
    hp[1] = __floats2half2_rn(sp2, sp3);
}

// --------------------------- readout + output LIF ---------------------------
__global__ void out_kernel(const float* __restrict__ Wout,
                           const float* __restrict__ bout,
                           const float* __restrict__ betas,
                           float* __restrict__ out, int t) {
    __shared__ float red[4][256];
    int b = blockIdx.x;
    int tid = threadIdx.x;
    const float* s = g_spk2 + (size_t)b * FOUT;
    const float4* W4 = (const float4*)Wout;
    float a0 = 0.f, a1 = 0.f, a2 = 0.f, a3 = 0.f;
    for (int k = tid; k < FOUT; k += 256) {
        float sv = s[k];
        float4 w = W4[k];
        a0 += sv * w.x; a1 += sv * w.y; a2 += sv * w.z; a3 += sv * w.w;
    }
    red[0][tid] = a0; red[1][tid] = a1; red[2][tid] = a2; red[3][tid] = a3;
    __syncthreads();
    for (int off = 128; off > 0; off >>= 1) {
        if (tid < off) {
#pragma unroll
            for (int q = 0; q < 4; q++) red[q][tid] += red[q][tid + off];
        }
        __syncthreads();
    }
    if (tid == 0) {
        float beta = clamp01(betas[3]);
#pragma unroll
        for (int n = 0; n < 4; n++) {
            float cur = red[n][0] + bout[n];
            float m = g_m_out[b * 4 + n];
            float mn = beta * m + cur - (m > 1.0f ? 1.0f : 0.f);
            g_m_out[b * 4 + n] = mn;
            out[t * BB * NCLS + b * NCLS + n] = (mn - 1.0f) > 0.f ? 1.f : 0.f;
        }
    }
}

// ------------------------------- launch -------------------------------------
extern "C" void kernel_launch(void* const* d_in, const int* in_sizes, int n_in,
                              void* d_out, int out_size) {
    const float* x     = (const float*)d_in[0];
    const float* W_in  = (const float*)d_in[1];
    const float* b_in  = (const float*)d_in[2];
    const float* W_h1  = (const float*)d_in[3];
    const float* b_h1  = (const float*)d_in[4];
    const float* W_h2  = (const float*)d_in[5];
    const float* b_h2  = (const float*)d_in[6];
    const float* W_out = (const float*)d_in[7];
    const float* b_out = (const float*)d_in[8];
    const float* betas = (const float*)d_in[9];
    const float* thrs  = (const float*)d_in[10];
    float* out = (float*)d_out;

    __half *p_feat_h, *p_feat_l, *p_spkin, *p_spk1;
    __half *p_Winh, *p_Winl, *p_Wh1h, *p_Wh1l, *p_Wh2h, *p_Wh2l;
    float *p_curin, *p_m_h1, *p_m_h2, *p_spk2;
    cudaGetSymbolAddress((void**)&p_feat_h, g_feat_h);
    cudaGetSymbolAddress((void**)&p_feat_l, g_feat_l);
    cudaGetSymbolAddress((void**)&p_curin,  g_curin);
    cudaGetSymbolAddress((void**)&p_spkin,  g_spkin_h);
    cudaGetSymbolAddress((void**)&p_spk1,   g_spk1_h);
    cudaGetSymbolAddress((void**)&p_m_h1,   g_m_h1);
    cudaGetSymbolAddress((void**)&p_spk2,   g_spk2);
    cudaGetSymbolAddress((void**)&p_m_h2,   g_m_h2);
    cudaGetSymbolAddress((void**)&p_Winh,   g_Win_h);
    cudaGetSymbolAddress((void**)&p_Winl,   g_Win_l);
    cudaGetSymbolAddress((void**)&p_Wh1h,   g_Wh1_h);
    cudaGetSymbolAddress((void**)&p_Wh1l,   g_Wh1_l);
    cudaGetSymbolAddress((void**)&p_Wh2h,   g_Wh2_h);
    cudaGetSymbolAddress((void**)&p_Wh2l,   g_Wh2_l);

    const int SMEM1 = NSTG * (2 * A_TILE_B + 2 * B_TILE_B);   // 92160 (split-A)
    const int SMEM2 = NSTG * (A_TILE_B + 2 * B_TILE_B);       // 61440
    cudaFuncSetAttribute(hgemm_kernel<true, 0>,
                         cudaFuncAttributeMaxDynamicSharedMemorySize, SMEM1);
    cudaFuncSetAttribute(hgemm_kernel<false, 1>,
                         cudaFuncAttributeMaxDynamicSharedMemorySize, SMEM2);
    cudaFuncSetAttribute(hgemm_kernel<false, 2>,
                         cudaFuncAttributeMaxDynamicSharedMemorySize, SMEM2);

    zero_kernel<<<512, 256>>>();

    // weight split+transpose (W [K,N] -> [N,K] fp16 hi/lo, scaled by 32)
    split_tr_kernel<<<dim3(H0F / 32, D_INF / 32), dim3(32, 8)>>>(W_in, p_Winh, p_Winl, D_INF, H0F);
    split_tr_kernel<<<dim3(H1F / 32, H0F / 32),  dim3(32, 8)>>>(W_h1, p_Wh1h, p_Wh1l, H0F, H1F);
    split_tr_kernel<<<dim3(H2F / 32, H1F / 32),  dim3(32, 8)>>>(W_h2, p_Wh2h, p_Wh2l, H1F, H2F);

    pool_kernel<<<T_STEPS * BB * CC * TPP, 256>>>(x);

    // GEMM1: cur_in_all = feat @ W_in + b_in   [14336, 2048], split-A 3-pass
    hgemm_kernel<true, 0><<<dim3(H0F / BNT, M_ALL / BMT), 256, SMEM1>>>(
        M_ALL, H0F, D_INF, p_feat_h, p_feat_l, p_Winh, p_Winl,
        b_in, p_curin, nullptr, nullptr, nullptr, 0, nullptr, 0);

    const int n4_lif_in = (MS * H0F) / 4;

    for (int t = 0; t < T_STEPS; t++) {
        lif_in_kernel<<<n4_lif_in / 256, 256>>>(betas, thrs, t);

        // GEMM2: spk_in @ W_h1 -> LIF -> spk1 (half)
        hgemm_kernel<false, 1><<<dim3(H1F / BNT, MS / BMT), 256, SMEM2>>>(
            MS, H1F, H0F, p_spkin, nullptr, p_Wh1h, p_Wh1l,
            b_h1, nullptr, p_m_h1, p_spk1, betas, 1, thrs, 1);

        // GEMM3: spk1 @ W_h2 -> LIF -> spk2 (float)
        hgemm_kernel<false, 2><<<dim3(H2F / BNT, MS / BMT), 256, SMEM2>>>(
            MS, H2F, H1F, p_spk1, nullptr, p_Wh2h, p_Wh2l,
            b_h2, nullptr, p_m_h2, p_spk2, betas, 2, thrs, 2);

        out_kernel<<<BB, 256>>>(W_out, b_out, betas, out, t);
    }
}